// round 16
// baseline (speedup 1.0000x reference)
#include <cuda_runtime.h>

// LSTM: B=32768, T=28, IN=28, H=8, gates i,j,f,o (cols 0-7,8-15,16-23,24-31).
// R16: TWO-PHASE split inside one kernel (R15 showed the batch x-GEMM (87%
// of FLOPs) trapped inside the serial loop, coupled to its registers: 197
// regs -> 2 CTAs/SM). Phase 1: per warp, compute pregates x_t*Wx+b for all
// 28 steps (pure FMA, no recurrence), reduced to 4 scalars/lane, stored IN
// PLACE over the x row (rows padded to 128B; 8 lanes' float4 = full row).
// Phase 2: recurrence reads pregates; per step only 16 h-fma2 + tanh tail.
// Wx (112 regs) and Wh (32 regs) have DISJOINT live ranges -> peak ~150
// regs -> launch_bounds(128,3) -> 3 CTAs/SM. smem 58.4KB dynamic.

#define T_STEPS 28
#define IN_DIM 28
#define NH 8
#define NC 10
#define TPB 128
#define ELEMS_PER_CTA 16                       // 4 warps * 4 elems
#define ROW_F 32                               // padded row: 32 floats = 128B
#define XP_FLOATS (ELEMS_PER_CTA * T_STEPS * ROW_F)   // 14336
#define SH_FLOATS (2 * ELEMS_PER_CTA * NH)             // 256
#define SMEM_BYTES ((XP_FLOATS + SH_FLOATS) * 4)       // 58368
#define X_F4_TOTAL (ELEMS_PER_CTA * T_STEPS * IN_DIM / 4)  // 3136

typedef unsigned long long u64;

__device__ __forceinline__ u64 pack2(float lo, float hi) {
    u64 r;
    asm("mov.b64 %0, {%1, %2};" : "=l"(r) : "f"(lo), "f"(hi));
    return r;
}
__device__ __forceinline__ void unpack2(u64 v, float& lo, float& hi) {
    asm("mov.b64 {%0, %1}, %2;" : "=f"(lo), "=f"(hi) : "l"(v));
}
__device__ __forceinline__ u64 fma2(u64 a, u64 b, u64 c) {
    u64 d;
    asm("fma.rn.f32x2 %0, %1, %2, %3;" : "=l"(d) : "l"(a), "l"(b), "l"(c));
    return d;
}
__device__ __forceinline__ float tanh_fast(float x) {
    float r;
    asm("tanh.approx.f32 %0, %1;" : "=f"(r) : "f"(x));
    return r;
}

__global__ void __launch_bounds__(TPB, 3)   // 170-reg cap -> 3 CTAs/SM
lstm_kernel(const float* __restrict__ x,
            const float* __restrict__ W,     // [36, 32] row-major
            const float* __restrict__ b,     // [32]
            const float* __restrict__ ow,    // [8, 10]
            const float* __restrict__ ob,    // [10]
            float* __restrict__ out,         // [B, 10]
            int B)
{
    extern __shared__ __align__(16) float smem[];
    float* sXP = smem;                         // [16][28][32] x -> pregates
    float* sH  = smem + XP_FLOATS;             // [2][16][8] h exchange

    const int tid = threadIdx.x;

    // ---- phase 0: stage x into padded rows (coalesced gmem reads) ----
    {
        const float4* gx = reinterpret_cast<const float4*>(
            x + (size_t)blockIdx.x * ELEMS_PER_CTA * (T_STEPS * IN_DIM));
        float4* sxp4 = reinterpret_cast<float4*>(sXP);
        for (int k = tid; k < X_F4_TOTAL; k += TPB) {
            int e = k / 49;          // 49 float4 per element (196/4)... no:
            // 196 floats per (elem? ) -- careful: per element 784 floats =
            // 196 float4; per (t): 7 float4.
            e = k / 196;
            int r = k - e * 196;
            int t = r / 7;
            int s = r - t * 7;
            sxp4[(e * T_STEPS + t) * 8 + s] = gx[k];
        }
    }

    const int lid = tid & 31;
    const int q   = lid & 7;                  // hidden unit this lane owns
    const int sub = lid >> 3;                 // element-in-warp 0..3
    const int elem_local = (tid >> 5) * 4 + sub;
    const int elem = blockIdx.x * ELEMS_PER_CTA + elem_local;

    // ---- x-part weights: rows 0..27 as 14 K-pairs x 4 gate columns ----
    // sigmoid columns (i,f,o) prescaled 0.5 for tanh-form sigmoid
    u64 wI[14], wJ[14], wF[14], wO[14];
#pragma unroll
    for (int m = 0; m < 14; m++) {
        wI[m] = pack2(0.5f * W[(2 * m) * 32 + q],
                      0.5f * W[(2 * m + 1) * 32 + q]);
        wJ[m] = pack2(W[(2 * m) * 32 + q + 8],
                      W[(2 * m + 1) * 32 + q + 8]);
        wF[m] = pack2(0.5f * W[(2 * m) * 32 + q + 16],
                      0.5f * W[(2 * m + 1) * 32 + q + 16]);
        wO[m] = pack2(0.5f * W[(2 * m) * 32 + q + 24],
                      0.5f * W[(2 * m + 1) * 32 + q + 24]);
    }
    const u64 aI0 = pack2(0.5f * b[q], 0.0f);
    const u64 aJ0 = pack2(b[q + 8], 0.0f);
    const u64 aF0 = pack2(0.5f * (b[q + 16] + 1.0f), 0.0f);  // FORGET_BIAS
    const u64 aO0 = pack2(0.5f * b[q + 24], 0.0f);

    __syncthreads();   // staging complete

    if (elem >= B) return;

    float4* rowb = reinterpret_cast<float4*>(sXP + elem_local * T_STEPS * ROW_F);

    // ---- phase 1: pregates for all steps, written in place over x ----
    // Same-warp in-order issue: all lanes' row reads precede the row STS.
#pragma unroll 2
    for (int t = 0; t < T_STEPS; t++) {
        const ulonglong2* xr =
            reinterpret_cast<const ulonglong2*>(rowb + t * 8);
        ulonglong2 xv0 = xr[0], xv1 = xr[1], xv2 = xr[2], xv3 = xr[3],
                   xv4 = xr[4], xv5 = xr[5], xv6 = xr[6];
        u64 aI = aI0, aJ = aJ0, aF = aF0, aO = aO0;
        u64 xk;
        xk = xv0.x; aI = fma2(xk, wI[0], aI);  aJ = fma2(xk, wJ[0], aJ);
                    aF = fma2(xk, wF[0], aF);  aO = fma2(xk, wO[0], aO);
        xk = xv0.y; aI = fma2(xk, wI[1], aI);  aJ = fma2(xk, wJ[1], aJ);
                    aF = fma2(xk, wF[1], aF);  aO = fma2(xk, wO[1], aO);
        xk = xv1.x; aI = fma2(xk, wI[2], aI);  aJ = fma2(xk, wJ[2], aJ);
                    aF = fma2(xk, wF[2], aF);  aO = fma2(xk, wO[2], aO);
        xk = xv1.y; aI = fma2(xk, wI[3], aI);  aJ = fma2(xk, wJ[3], aJ);
                    aF = fma2(xk, wF[3], aF);  aO = fma2(xk, wO[3], aO);
        xk = xv2.x; aI = fma2(xk, wI[4], aI);  aJ = fma2(xk, wJ[4], aJ);
                    aF = fma2(xk, wF[4], aF);  aO = fma2(xk, wO[4], aO);
        xk = xv2.y; aI = fma2(xk, wI[5], aI);  aJ = fma2(xk, wJ[5], aJ);
                    aF = fma2(xk, wF[5], aF);  aO = fma2(xk, wO[5], aO);
        xk = xv3.x; aI = fma2(xk, wI[6], aI);  aJ = fma2(xk, wJ[6], aJ);
                    aF = fma2(xk, wF[6], aF);  aO = fma2(xk, wO[6], aO);
        xk = xv3.y; aI = fma2(xk, wI[7], aI);  aJ = fma2(xk, wJ[7], aJ);
                    aF = fma2(xk, wF[7], aF);  aO = fma2(xk, wO[7], aO);
        xk = xv4.x; aI = fma2(xk, wI[8], aI);  aJ = fma2(xk, wJ[8], aJ);
                    aF = fma2(xk, wF[8], aF);  aO = fma2(xk, wO[8], aO);
        xk = xv4.y; aI = fma2(xk, wI[9], aI);  aJ = fma2(xk, wJ[9], aJ);
                    aF = fma2(xk, wF[9], aF);  aO = fma2(xk, wO[9], aO);
        xk = xv5.x; aI = fma2(xk, wI[10], aI); aJ = fma2(xk, wJ[10], aJ);
                    aF = fma2(xk, wF[10], aF); aO = fma2(xk, wO[10], aO);
        xk = xv5.y; aI = fma2(xk, wI[11], aI); aJ = fma2(xk, wJ[11], aJ);
                    aF = fma2(xk, wF[11], aF); aO = fma2(xk, wO[11], aO);
        xk = xv6.x; aI = fma2(xk, wI[12], aI); aJ = fma2(xk, wJ[12], aJ);
                    aF = fma2(xk, wF[12], aF); aO = fma2(xk, wO[12], aO);
        xk = xv6.y; aI = fma2(xk, wI[13], aI); aJ = fma2(xk, wJ[13], aJ);
                    aF = fma2(xk, wF[13], aF); aO = fma2(xk, wO[13], aO);

        float lo, hi;
        float4 pg;
        unpack2(aI, lo, hi); pg.x = lo + hi;
        unpack2(aJ, lo, hi); pg.y = lo + hi;
        unpack2(aF, lo, hi); pg.z = lo + hi;
        unpack2(aO, lo, hi); pg.w = lo + hi;
        rowb[t * 8 + q] = pg;                 // STS.128 in place
    }

    // ---- h-part weights: rows 28..35 as 4 K-pairs x 4 gates ----
    // (loaded AFTER phase 1 so Wx/Wh register live ranges stay disjoint)
    u64 hI[4], hJ[4], hF[4], hO[4];
#pragma unroll
    for (int m = 0; m < 4; m++) {
        int r0 = 28 + 2 * m, r1 = 29 + 2 * m;
        hI[m] = pack2(0.5f * W[r0 * 32 + q],      0.5f * W[r1 * 32 + q]);
        hJ[m] = pack2(W[r0 * 32 + q + 8],         W[r1 * 32 + q + 8]);
        hF[m] = pack2(0.5f * W[r0 * 32 + q + 16], 0.5f * W[r1 * 32 + q + 16]);
        hO[m] = pack2(0.5f * W[r0 * 32 + q + 24], 0.5f * W[r1 * 32 + q + 24]);
    }

    // ---- phase 2: recurrence over pregates ----
    u64 hk[4];
#pragma unroll
    for (int m = 0; m < 4; m++) hk[m] = 0ull;
    float c = 0.0f;

#pragma unroll 2
    for (int t = 0; t < T_STEPS; t++) {
        float4 pg = rowb[t * 8 + q];          // this lane's own pregates

        u64 aI = fma2(hk[0], hI[0], 0ull);
        u64 aJ = fma2(hk[0], hJ[0], 0ull);
        u64 aF = fma2(hk[0], hF[0], 0ull);
        u64 aO = fma2(hk[0], hO[0], 0ull);
        aI = fma2(hk[1], hI[1], aI); aJ = fma2(hk[1], hJ[1], aJ);
        aF = fma2(hk[1], hF[1], aF); aO = fma2(hk[1], hO[1], aO);
        aI = fma2(hk[2], hI[2], aI); aJ = fma2(hk[2], hJ[2], aJ);
        aF = fma2(hk[2], hF[2], aF); aO = fma2(hk[2], hO[2], aO);
        aI = fma2(hk[3], hI[3], aI); aJ = fma2(hk[3], hJ[3], aJ);
        aF = fma2(hk[3], hF[3], aF); aO = fma2(hk[3], hO[3], aO);

        float lo, hi;
        unpack2(aI, lo, hi); float gi = pg.x + lo + hi;
        unpack2(aJ, lo, hi); float gj = pg.y + lo + hi;
        unpack2(aF, lo, hi); float gf = pg.z + lo + hi;
        unpack2(aO, lo, hi); float go = pg.w + lo + hi;

        float si = fmaf(0.5f, tanh_fast(gi), 0.5f);
        float tj = tanh_fast(gj);
        float sf = fmaf(0.5f, tanh_fast(gf), 0.5f);
        float so = fmaf(0.5f, tanh_fast(go), 0.5f);

        float cn = c * sf + si * tj;
        c = cn;
        float h = tanh_fast(cn) * so;

        // h exchange: double-buffered smem, single syncwarp
        float* buf = sH + (t & 1) * (ELEMS_PER_CTA * NH) + elem_local * NH;
        buf[q] = h;
        __syncwarp();
        const ulonglong2* hv = reinterpret_cast<const ulonglong2*>(buf);
        ulonglong2 h01 = hv[0];
        ulonglong2 h23 = hv[1];
        hk[0] = h01.x; hk[1] = h01.y; hk[2] = h23.x; hk[3] = h23.y;
    }

    // ---- output projection: lane q does class q; lanes 0,1 also 8,9 ----
    {
        float h0, h1, h2, h3, h4, h5, h6, h7;
        float lo, hi;
        unpack2(hk[0], lo, hi); h0 = lo; h1 = hi;
        unpack2(hk[1], lo, hi); h2 = lo; h3 = hi;
        unpack2(hk[2], lo, hi); h4 = lo; h5 = hi;
        unpack2(hk[3], lo, hi); h6 = lo; h7 = hi;

#pragma unroll
        for (int rep = 0; rep < 2; rep++) {
            int cls = (rep == 0) ? q : (8 + q);
            if (rep == 0 || q < 2) {
                float a = ob[cls];
                a += h0 * ow[0 * NC + cls];
                a += h1 * ow[1 * NC + cls];
                a += h2 * ow[2 * NC + cls];
                a += h3 * ow[3 * NC + cls];
                a += h4 * ow[4 * NC + cls];
                a += h5 * ow[5 * NC + cls];
                a += h6 * ow[6 * NC + cls];
                a += h7 * ow[7 * NC + cls];
                out[(size_t)elem * NC + cls] = a;
            }
        }
    }
}

extern "C" void kernel_launch(void* const* d_in, const int* in_sizes, int n_in,
                              void* d_out, int out_size) {
    const float* x  = (const float*)d_in[0];
    const float* W  = (const float*)d_in[1];
    const float* b  = (const float*)d_in[2];
    const float* ow = (const float*)d_in[3];
    const float* ob = (const float*)d_in[4];
    float* out = (float*)d_out;

    cudaFuncSetAttribute(lstm_kernel,
                         cudaFuncAttributeMaxDynamicSharedMemorySize,
                         SMEM_BYTES);

    const int B = in_sizes[0] / (T_STEPS * IN_DIM);
    const int grid = (B + ELEMS_PER_CTA - 1) / ELEMS_PER_CTA;
    lstm_kernel<<<grid, TPB, SMEM_BYTES>>>(x, W, b, ow, ob, out, B);
}

// round 17
// speedup vs baseline: 1.0324x; 1.0324x over previous
#include <cuda_runtime.h>

// LSTM: B=32768, T=28, IN=28, H=8, gates i,j,f,o (cols 0-7,8-15,16-23,24-31).
// R17 = R15 (lane q owns all 4 gates of unit q, 4x18 K-packed f32x2 weight
// regs, 4 elems/warp, x staged in smem, t+1 x-GEMM pipelined into the
// h-tail, dbl-buffered sH, tanh.approx w/ 0.5-prescaled sigmoid cols) with
// REGISTER TRIM to reach 3 CTAs/SM (R15: 197 regs -> 2 CTAs, fma 50.6%):
//   - x buffer 7x ulonglong2 -> 2-reg alternating pipeline   (-20 regs)
//   - packed bias seeds -> 4 scalar biases added at reduce   (-4 regs)
// launch_bounds(128,3): cap 170 = 3*128*170 <= 64K regfile. R16's split
// (3 CTAs but +port +instr) regressed; this keeps R15's fused structure.

#define T_STEPS 28
#define IN_DIM 28
#define NH 8
#define NC 10
#define TPB 128
#define ELEMS_PER_CTA 16                      // 4 warps * 4 elems
#define X_FLOATS_PER_ELEM (T_STEPS * IN_DIM)  // 784
#define X_F4_PER_CTA (ELEMS_PER_CTA * X_FLOATS_PER_ELEM / 4)  // 3136

typedef unsigned long long u64;

__device__ __forceinline__ u64 pack2(float lo, float hi) {
    u64 r;
    asm("mov.b64 %0, {%1, %2};" : "=l"(r) : "f"(lo), "f"(hi));
    return r;
}
__device__ __forceinline__ void unpack2(u64 v, float& lo, float& hi) {
    asm("mov.b64 {%0, %1}, %2;" : "=f"(lo), "=f"(hi) : "l"(v));
}
__device__ __forceinline__ u64 fma2(u64 a, u64 b, u64 c) {
    u64 d;
    asm("fma.rn.f32x2 %0, %1, %2, %3;" : "=l"(d) : "l"(a), "l"(b), "l"(c));
    return d;
}
__device__ __forceinline__ float tanh_fast(float x) {
    float r;
    asm("tanh.approx.f32 %0, %1;" : "=f"(r) : "f"(x));
    return r;
}

// 8 fma2: consume one ulonglong2 (K-pairs m, m+1) into the 4 x-accumulators
#define XPAIR(xv, m)                                                   \
    do {                                                               \
        xI = fma2((xv).x, wI[(m)],     xI);                            \
        xJ = fma2((xv).x, wJ[(m)],     xJ);                            \
        xF = fma2((xv).x, wF[(m)],     xF);                            \
        xO = fma2((xv).x, wO[(m)],     xO);                            \
        xI = fma2((xv).y, wI[(m) + 1], xI);                            \
        xJ = fma2((xv).y, wJ[(m) + 1], xJ);                            \
        xF = fma2((xv).y, wF[(m) + 1], xF);                            \
        xO = fma2((xv).y, wO[(m) + 1], xO);                            \
    } while (0)

__global__ void __launch_bounds__(TPB, 3)   // 170-reg cap -> 3 CTAs/SM
lstm_kernel(const float* __restrict__ x,
            const float* __restrict__ W,     // [36, 32] row-major
            const float* __restrict__ b,     // [32]
            const float* __restrict__ ow,    // [8, 10]
            const float* __restrict__ ob,    // [10]
            float* __restrict__ out,         // [B, 10]
            int B)
{
    __shared__ __align__(16) float sX[ELEMS_PER_CTA * X_FLOATS_PER_ELEM];
    __shared__ __align__(16) float sH[2][ELEMS_PER_CTA * NH];  // dbl-buffered

    const int tid = threadIdx.x;

    // ---- bulk-stage this CTA's x: 50KB, fully coalesced, deep MLP ----
    {
        const float4* __restrict__ gx = reinterpret_cast<const float4*>(
            x + (size_t)blockIdx.x * ELEMS_PER_CTA * X_FLOATS_PER_ELEM);
        float4* sx4 = reinterpret_cast<float4*>(sX);
#pragma unroll
        for (int i = 0; i < X_F4_PER_CTA / TPB; i++)          // 24 iters
            sx4[i * TPB + tid] = gx[i * TPB + tid];
        if (tid < X_F4_PER_CTA - (X_F4_PER_CTA / TPB) * TPB)  // 64 rem
            sx4[(X_F4_PER_CTA / TPB) * TPB + tid] =
                gx[(X_F4_PER_CTA / TPB) * TPB + tid];
    }

    const int lid = tid & 31;
    const int q   = lid & 7;                  // hidden unit this lane owns
    const int sub = lid >> 3;                 // element-in-warp 0..3
    const int elem_local = (tid >> 5) * 4 + sub;
    const int elem = blockIdx.x * ELEMS_PER_CTA + elem_local;

    // ---- 4 gate columns of hidden unit q, K-packed f32x2, in registers ----
    // sigmoid columns (i,f,o) prescaled 0.5 for the tanh-form sigmoid
    u64 wI[18], wJ[18], wF[18], wO[18];
#pragma unroll
    for (int m = 0; m < 18; m++) {
        wI[m] = pack2(0.5f * W[(2 * m) * 32 + q],
                      0.5f * W[(2 * m + 1) * 32 + q]);
        wJ[m] = pack2(W[(2 * m) * 32 + q + 8],
                      W[(2 * m + 1) * 32 + q + 8]);
        wF[m] = pack2(0.5f * W[(2 * m) * 32 + q + 16],
                      0.5f * W[(2 * m + 1) * 32 + q + 16]);
        wO[m] = pack2(0.5f * W[(2 * m) * 32 + q + 24],
                      0.5f * W[(2 * m + 1) * 32 + q + 24]);
    }
    // scalar biases, added at the reduce (saves 4 regs vs packed seeds)
    const float bI = 0.5f * b[q];
    const float bJ = b[q + 8];
    const float bF = 0.5f * (b[q + 16] + 1.0f);   // FORGET_BIAS baked in
    const float bO = 0.5f * b[q + 24];

    __syncthreads();   // staging complete

    if (elem >= B) return;

    const ulonglong2* __restrict__ xs = reinterpret_cast<const ulonglong2*>(
        sX + elem_local * X_FLOATS_PER_ELEM);

    u64 hk[4];                      // h as 4 packed pairs (h0,h1)..(h6,h7)
#pragma unroll
    for (int m = 0; m < 4; m++) hk[m] = 0ull;
    float c = 0.0f;

    // ---- prologue: x-part of step 0 (alternating 2-reg load pipeline) ----
    u64 xI = 0ull, xJ = 0ull, xF = 0ull, xO = 0ull;
    {
        ulonglong2 xa = xs[0];
        ulonglong2 xb = xs[1];
        XPAIR(xa, 0);  xa = xs[2];
        XPAIR(xb, 2);  xb = xs[3];
        XPAIR(xa, 4);  xa = xs[4];
        XPAIR(xb, 6);  xb = xs[5];
        XPAIR(xa, 8);  xa = xs[6];
        XPAIR(xb, 10);
        XPAIR(xa, 12);
    }

#pragma unroll 1
    for (int t = 0; t < T_STEPS; t++) {
        // full gates: h contribution onto the pipelined x-part
        u64 aI = xI, aJ = xJ, aF = xF, aO = xO;
#pragma unroll
        for (int m = 0; m < 4; m++) {
            aI = fma2(hk[m], wI[14 + m], aI);
            aJ = fma2(hk[m], wJ[14 + m], aJ);
            aF = fma2(hk[m], wF[14 + m], aF);
            aO = fma2(hk[m], wO[14 + m], aO);
        }

        // pipeline: x-part for t+1 (independent of h; fills tail stalls)
        {
            const int tn = (t < T_STEPS - 1) ? t + 1 : t;
            const ulonglong2* __restrict__ xr = xs + tn * 7;
            xI = 0ull; xJ = 0ull; xF = 0ull; xO = 0ull;
            ulonglong2 xa = xr[0];
            ulonglong2 xb = xr[1];
            XPAIR(xa, 0);  xa = xr[2];
            XPAIR(xb, 2);  xb = xr[3];
            XPAIR(xa, 4);  xa = xr[4];
            XPAIR(xb, 6);  xb = xr[5];
            XPAIR(xa, 8);  xa = xr[6];
            XPAIR(xb, 10);
            XPAIR(xa, 12);
        }

        // tail: reduce (+bias), activations, state update
        float lo, hi;
        unpack2(aI, lo, hi); float gi = bI + lo + hi;
        unpack2(aJ, lo, hi); float gj = bJ + lo + hi;
        unpack2(aF, lo, hi); float gf = bF + lo + hi;
        unpack2(aO, lo, hi); float go = bO + lo + hi;

        float si = fmaf(0.5f, tanh_fast(gi), 0.5f);
        float tj = tanh_fast(gj);
        float sf = fmaf(0.5f, tanh_fast(gf), 0.5f);
        float so = fmaf(0.5f, tanh_fast(go), 0.5f);

        float cn = c * sf + si * tj;
        c = cn;
        float h = tanh_fast(cn) * so;

        // h exchange: double-buffered -> single syncwarp per step
        float* sHb = sH[t & 1];
        sHb[elem_local * NH + q] = h;
        __syncwarp();
        const ulonglong2* hvb = reinterpret_cast<const ulonglong2*>(
            sHb + elem_local * NH);
        ulonglong2 h01 = hvb[0];
        ulonglong2 h23 = hvb[1];
        hk[0] = h01.x; hk[1] = h01.y; hk[2] = h23.x; hk[3] = h23.y;
    }

    // output projection: lane q does class q; lanes 0,1 also classes 8,9
    {
        float h0, h1, h2, h3, h4, h5, h6, h7;
        float lo, hi;
        unpack2(hk[0], lo, hi); h0 = lo; h1 = hi;
        unpack2(hk[1], lo, hi); h2 = lo; h3 = hi;
        unpack2(hk[2], lo, hi); h4 = lo; h5 = hi;
        unpack2(hk[3], lo, hi); h6 = lo; h7 = hi;

#pragma unroll
        for (int rep = 0; rep < 2; rep++) {
            int cls = (rep == 0) ? q : (8 + q);
            if (rep == 0 || q < 2) {
                float a = ob[cls];
                a += h0 * ow[0 * NC + cls];
                a += h1 * ow[1 * NC + cls];
                a += h2 * ow[2 * NC + cls];
                a += h3 * ow[3 * NC + cls];
                a += h4 * ow[4 * NC + cls];
                a += h5 * ow[5 * NC + cls];
                a += h6 * ow[6 * NC + cls];
                a += h7 * ow[7 * NC + cls];
                out[(size_t)elem * NC + cls] = a;
            }
        }
    }
}

extern "C" void kernel_launch(void* const* d_in, const int* in_sizes, int n_in,
                              void* d_out, int out_size) {
    const float* x  = (const float*)d_in[0];
    const float* W  = (const float*)d_in[1];
    const float* b  = (const float*)d_in[2];
    const float* ow = (const float*)d_in[3];
    const float* ob = (const float*)d_in[4];
    float* out = (float*)d_out;

    const int B = in_sizes[0] / (T_STEPS * IN_DIM);
    const int grid = (B + ELEMS_PER_CTA - 1) / ELEMS_PER_CTA;
    lstm_kernel<<<grid, TPB>>>(x, W, b, ow, ob, out, B);
}